// round 6
// baseline (speedup 1.0000x reference)
#include <cuda_runtime.h>

#define Bn 4
#define Pn 8
#define Vn 2048
#define En 2048
#define Fn 4096
#define TILES 2
#define SPLIT 2
#define TPB 512              // 16 warps -> 4 warps per SMSP
#define VPT 2                // 1024 verts per block
#define EMAX 1028            // half-table cap (1024) + pad
#define NGROUP (Bn * Pn * TILES)          // 64 (b,p,tile) groups
#define CHAM_BLOCKS (NGROUP * SPLIT)      // 128
#define BIGF 3.402823466e38f

__device__ float g_pmin[SPLIT][NGROUP][TPB * VPT];   // per-half per-vertex mins
__device__ unsigned int g_gc[NGROUP];                // per-group arrival counters
__device__ float g_part_sum[NGROUP];
__device__ float g_part_cnt[NGROUP];
__device__ unsigned int g_counter;                   // combine events; never reset

// ---------------------------------------------------------------------------
__device__ __forceinline__ unsigned long long bcast2(float v) {
    unsigned long long r;
    asm("mov.b64 %0, {%1, %1};" : "=l"(r) : "f"(v));
    return r;
}

// d2[k] = px*x2[k] + py*y2[k] + c2[k]  for k=0,1 ; fold into mins
__device__ __forceinline__ void edge2(float& m0, float& m1,
                                      unsigned long long pxx, unsigned long long pyy,
                                      unsigned long long x2, unsigned long long y2,
                                      unsigned long long c2)
{
    float d0, d1;
    asm("{\n\t"
        ".reg .b64 t;\n\t"
        "fma.rn.f32x2 t, %2, %3, %4;\n\t"
        "fma.rn.f32x2 t, %5, %6, t;\n\t"
        "mov.b64 {%0, %1}, t;\n\t"
        "}"
        : "=f"(d0), "=f"(d1)
        : "l"(pyy), "l"(y2), "l"(c2), "l"(pxx), "l"(x2));
    m0 = fminf(m0, d0);
    m1 = fminf(m1, d1);
}

// ---------------------------------------------------------------------------
// Blocks [0,128): chamfer (edge-split siblings). Blocks [128,132): volume.
// ---------------------------------------------------------------------------
__global__ void __launch_bounds__(TPB)
fused_kernel(const float* __restrict__ xs,
             const float* __restrict__ pm,
             const float* __restrict__ em,
             const int*   __restrict__ lens,
             const void*  __restrict__ bmask,
             const int*   __restrict__ faces,
             const float* __restrict__ tv,
             float* __restrict__ out)
{
    const int bx  = blockIdx.x;
    const int tid = threadIdx.x;

    // =========================== VOLUME BLOCKS ============================
    if (bx >= CHAM_BLOCKS) {
        __shared__ double sred[TPB];
        const int b = bx - CHAM_BLOCKS;
        const float* base = xs + (size_t)b * Vn * 3;
        double acc = 0.0;
        for (int f = tid; f < Fn; f += TPB) {
            const int* fi = faces + ((size_t)b * Fn + f) * 3;
            const float* a0 = base + (size_t)fi[0] * 3;
            const float* a1 = base + (size_t)fi[1] * 3;
            const float* a2 = base + (size_t)fi[2] * 3;
            const float v0x = a0[0], v0y = a0[1], v0z = a0[2];
            const float v1x = a1[0], v1y = a1[1], v1z = a1[2];
            const float v2x = a2[0], v2y = a2[1], v2z = a2[2];
            const float cx = v0y * v1z - v0z * v1y;
            const float cy = v0z * v1x - v0x * v1z;
            const float cz = v0x * v1y - v0y * v1x;
            acc += (double)((cx * v2x + cy * v2y + cz * v2z) * (1.0f / 6.0f));
        }
        sred[tid] = acc;
        __syncthreads();
        #pragma unroll
        for (int s = TPB / 2; s >= 1; s >>= 1) {
            if (tid < s) sred[tid] += sred[tid + s];
            __syncthreads();
        }
        if (tid == 0) {
            float vols = fabsf((float)sred[0]);
            float d = vols - tv[b];
            out[4 + b] = d * d;
        }
        return;
    }

    // =========================== CHAMFER BLOCKS ===========================
    __shared__ __align__(16) float s_c[EMAX];
    __shared__ __align__(16) float s_x[EMAX];
    __shared__ __align__(16) float s_y[EMAX];
    __shared__ float s_rs[TPB / 32], s_rc[TPB / 32];
    __shared__ int   s_second, s_lastg;

    const int s    = bx & (SPLIT - 1);
    const int tile = (bx >> 1) & (TILES - 1);
    const int p    = (bx >> 2) & (Pn - 1);
    const int b    = bx >> 5;
    const int group = (b * Pn + p) * TILES + tile;

    // ---- edge half-range ----
    const int L     = lens[b * Pn + p];
    const int half  = (L + 1) >> 1;
    const int start = s ? half : 0;
    const int len   = s ? (L - half) : half;
    const int len4  = (len + 3) & ~3;

    // ---- preload + transform this half's edge table ----
    const float2* embase = (const float2*)(em + ((size_t)(b * Pn + p)) * En * 2);
    for (int i = tid; i < len; i += TPB) {
        float2 e = embase[start + i];
        s_c[i] = fmaf(e.x, e.x, e.y * e.y);
        s_x[i] = -2.0f * e.x;
        s_y[i] = -2.0f * e.y;
    }
    for (int i = len + tid; i < len4; i += TPB) {   // BIG pad -> no tail loop
        s_c[i] = BIGF; s_x[i] = 0.0f; s_y[i] = 0.0f;
    }

    // ---- boundary_mask layout detection (first 4KB) ----
    unsigned int scan = 0;
    {
        const unsigned int* mw = (const unsigned int*)bmask;
        #pragma unroll
        for (int i = tid; i < 1024; i += TPB)
            scan |= (mw[i] & 0xFFFFFF00u);
    }
    const int mask_is_bytes = __syncthreads_or(scan != 0);  // also the preload barrier

    // ---- per-thread vertex projections ----
    const float* M = pm + p * 12;
    const int vbase = tile * (TPB * VPT);
    float px[VPT], py[VPT], ppv[VPT];
    unsigned long long pxx[VPT], pyy[VPT];
    #pragma unroll
    for (int j = 0; j < VPT; ++j) {
        const int v = vbase + j * TPB + tid;
        const float* xv = xs + ((size_t)b * Vn + v) * 3;
        const float x = xv[0], y = xv[1], z = xv[2];
        const float q0 = M[0] * x + M[1] * y + M[2]  * z + M[3];
        const float q1 = M[4] * x + M[5] * y + M[6]  * z + M[7];
        const float q2 = M[8] * x + M[9] * y + M[10] * z + M[11];
        px[j] = q0 / q2;
        py[j] = q1 / q2;
        ppv[j] = fmaf(px[j], px[j], py[j] * py[j]);
        pxx[j] = bcast2(px[j]);
        pyy[j] = bcast2(py[j]);
    }

    // ---- main loop: 4 edges x 2 verts per iteration ----
    const int NI = len4 >> 2;
    float ma[VPT], mb[VPT], mc[VPT], md[VPT];
    #pragma unroll
    for (int j = 0; j < VPT; ++j) { ma[j] = BIGF; mb[j] = BIGF; mc[j] = BIGF; md[j] = BIGF; }

    const ulonglong2* pc  = (const ulonglong2*)s_c;
    const ulonglong2* pxv = (const ulonglong2*)s_x;
    const ulonglong2* pyv = (const ulonglong2*)s_y;

    #pragma unroll 2
    for (int i = 0; i < NI; ++i) {
        const ulonglong2 c4 = pc[i];
        const ulonglong2 x4 = pxv[i];
        const ulonglong2 y4 = pyv[i];
        #pragma unroll
        for (int j = 0; j < VPT; ++j) {
            edge2(ma[j], mb[j], pxx[j], pyy[j], x4.x, y4.x, c4.x);
            edge2(mc[j], md[j], pxx[j], pyy[j], x4.y, y4.y, c4.y);
        }
    }

    // ---- per-vertex half-min (+ |p|^2 so halves are directly comparable) ----
    float dh[VPT];
    #pragma unroll
    for (int j = 0; j < VPT; ++j) {
        dh[j] = fminf(fminf(ma[j], mb[j]), fminf(mc[j], md[j])) + ppv[j];
        g_pmin[s][group][j * TPB + tid] = dh[j];
    }
    __threadfence();
    if (tid == 0) {
        unsigned int old = atomicAdd(&g_gc[group], 1u);
        s_second = (((old + 1u) & 1u) == 0u) ? 1 : 0;   // both siblings arrived
    }
    __syncthreads();
    if (!s_second) return;

    // ---- second finisher: combine with sibling, mask, reduce ----
    __threadfence();
    const float* sib = g_pmin[s ^ 1][group];
    float cs = 0.0f, cc = 0.0f;
    #pragma unroll
    for (int j = 0; j < VPT; ++j) {
        const float dmin = fminf(dh[j], sib[j * TPB + tid]);
        const int v = vbase + j * TPB + tid;
        const int midx = (b * Pn + p) * Vn + v;
        float w;
        if (mask_is_bytes) w = (((const unsigned char*)bmask)[midx] != 0) ? 1.0f : 0.0f;
        else               w = (((const int*)bmask)[midx] != 0) ? 1.0f : 0.0f;
        cs = fmaf(w, dmin, cs);
        cc += w;
    }

    #pragma unroll
    for (int off = 16; off >= 1; off >>= 1) {
        cs += __shfl_down_sync(0xffffffffu, cs, off);
        cc += __shfl_down_sync(0xffffffffu, cc, off);
    }
    const int wid = tid >> 5;
    if ((tid & 31) == 0) { s_rs[wid] = cs; s_rc[wid] = cc; }
    __syncthreads();

    if (tid == 0) {
        float ts = 0.0f, tc = 0.0f;
        #pragma unroll
        for (int i = 0; i < TPB / 32; ++i) { ts += s_rs[i]; tc += s_rc[i]; }
        g_part_sum[group] = ts;
        g_part_cnt[group] = tc;
        __threadfence();
        unsigned int old = atomicAdd(&g_counter, 1u);
        s_lastg = (((old + 1u) & (NGROUP - 1u)) == 0u) ? 1 : 0;
    }
    __syncthreads();

    // ---- last combiner finalizes chamfer means ----
    if (s_lastg && tid < 32) {
        __threadfence();
        const int lane = tid;                    // lane = b*Pn + p
        float su = 0.0f, ct = 0.0f;
        #pragma unroll
        for (int t = 0; t < TILES; ++t) {
            su += g_part_sum[lane * TILES + t];
            ct += g_part_cnt[lane * TILES + t];
        }
        float ppj = su / fmaxf(ct, 1.0f);
        #pragma unroll
        for (int off = 4; off >= 1; off >>= 1)
            ppj += __shfl_down_sync(0xffffffffu, ppj, off, 8);
        if ((lane & 7) == 0) out[lane >> 3] = ppj * (1.0f / Pn);
    }
}

// ---------------------------------------------------------------------------
extern "C" void kernel_launch(void* const* d_in, const int* in_sizes, int n_in,
                              void* d_out, int out_size)
{
    const float* xs    = (const float*)d_in[0];   // (4,2048,3)
    const float* pm    = (const float*)d_in[1];   // (8,3,4)
    const float* em    = (const float*)d_in[2];   // (4,8,2048,2)
    const int*   lens  = (const int*)  d_in[3];   // (4,8)
    const void*  bmask =               d_in[4];   // (4,8,2048) bool (layout auto-detected)
    const int*   faces = (const int*)  d_in[5];   // (4,4096,3)
    const float* tv    = (const float*)d_in[6];   // (4,)
    float* out = (float*)d_out;                   // [chamfer(4), vol_error(4)]

    fused_kernel<<<CHAM_BLOCKS + Bn, TPB>>>(xs, pm, em, lens, bmask, faces, tv, out);
}